// round 6
// baseline (speedup 1.0000x reference)
#include <cuda_runtime.h>
#include <math.h>

#define NP 2048
#define IMG 128
#define NPIX (IMG*IMG)
#define TW 16
#define TH 8
#define NTX 8
#define NTY 16
#define NTILES (NTX*NTY)     // 128 == grid size
#define NB 128
#define NT 128
#define MWORDS 64            // 2048 bits / 32
#define LISTCAP 128
#define GPB (NP / NB)        // 16 gaussians per block

// Unsorted per-gaussian data
__device__ float4 g_PA[NP], g_PB[NP], g_PBB[NP];
__device__ float  g_Pcb[NP];
__device__ unsigned long long g_key[NP];
// Sorted copies
__device__ float4 g_SA[NP], g_SB[NP];
__device__ float  g_Scb[NP];
// Per-tile bitmask over sorted ranks
__device__ unsigned g_mask[NTILES * MWORDS];
// Grid barrier state (zero-init; generation counters never need reset)
__device__ unsigned g_cnt[2];
__device__ unsigned g_gen[2];

__device__ __forceinline__ void grid_barrier(int k)
{
    __syncthreads();
    if (threadIdx.x == 0) {
        unsigned gen = ((volatile unsigned*)g_gen)[k];
        unsigned my  = atomicAdd(&g_cnt[k], 1u);
        if (my == NB - 1) {
            g_cnt[k] = 0;
            __threadfence();
            atomicExch(&g_gen[k], gen + 1u);
        } else {
            while (((volatile unsigned*)g_gen)[k] == gen) { __nanosleep(32); }
        }
        __threadfence();
    }
    __syncthreads();
}

__global__ __launch_bounds__(NT)
void fused_kernel(const float* __restrict__ means,
                  const float* __restrict__ feats,
                  const float* __restrict__ ops,
                  const float* __restrict__ scales,
                  const float* __restrict__ rots,
                  const float* __restrict__ V,
                  const float* __restrict__ PM,
                  float* __restrict__ out)
{
    __shared__ unsigned long long s_keys[NP];      // 16KB (phase 2)
    __shared__ unsigned smask[MWORDS];
    __shared__ int sofs[MWORDS + 1];
    __shared__ float4 lA[LISTCAP], lB[LISTCAP];
    __shared__ float  lCb[LISTCAP];

    int tid = threadIdx.x;
    int blk = blockIdx.x;
    float* out_radii = out + 3 * NPIX;

    // ================= Phase 1: preprocess (16 gaussians per block) ========
    // zero this block's mask slice (64 words)
    if (tid < MWORDS) g_mask[blk * MWORDS + tid] = 0u;

    if (tid < GPB) {
        int i = blk * GPB + tid;

        const float tanfov = 0.57735026918962576f;
        const float fx = (float)IMG / (2.0f * tanfov);
        const float fy = fx;

        float mx = means[3*i], my = means[3*i+1], mz = means[3*i+2];

        float t0 = V[0]*mx + V[1]*my + V[2]*mz + V[3];
        float t1 = V[4]*mx + V[5]*my + V[6]*mz + V[7];
        float t2 = V[8]*mx + V[9]*my + V[10]*mz + V[11];
        float depth = t2;

        float ph0 = PM[0]*mx + PM[1]*my + PM[2]*mz + PM[3];
        float ph1 = PM[4]*mx + PM[5]*my + PM[6]*mz + PM[7];
        float pw  = PM[12]*mx + PM[13]*my + PM[14]*mz + PM[15];
        float invpw = 1.0f / (pw + 1e-7f);
        float px = ((ph0*invpw + 1.0f) * (float)IMG - 1.0f) * 0.5f;
        float py = ((ph1*invpw + 1.0f) * (float)IMG - 1.0f) * 0.5f;

        float qw = rots[4*i], qx = rots[4*i+1], qy = rots[4*i+2], qz = rots[4*i+3];
        float qn = rsqrtf(qw*qw + qx*qx + qy*qy + qz*qz);
        qw *= qn; qx *= qn; qy *= qn; qz *= qn;
        float R00 = 1.0f - 2.0f*(qy*qy + qz*qz);
        float R01 = 2.0f*(qx*qy - qw*qz);
        float R02 = 2.0f*(qx*qz + qw*qy);
        float R10 = 2.0f*(qx*qy + qw*qz);
        float R11 = 1.0f - 2.0f*(qx*qx + qz*qz);
        float R12 = 2.0f*(qy*qz - qw*qx);
        float R20 = 2.0f*(qx*qz - qw*qy);
        float R21 = 2.0f*(qy*qz + qw*qx);
        float R22 = 1.0f - 2.0f*(qx*qx + qy*qy);

        float s0 = scales[3*i], s1 = scales[3*i+1], s2 = scales[3*i+2];
        float M00 = R00*s0, M01 = R01*s1, M02 = R02*s2;
        float M10 = R10*s0, M11 = R11*s1, M12 = R12*s2;
        float M20 = R20*s0, M21 = R21*s1, M22 = R22*s2;

        float s00 = M00*M00 + M01*M01 + M02*M02;
        float s01 = M00*M10 + M01*M11 + M02*M12;
        float s02 = M00*M20 + M01*M21 + M02*M22;
        float s11 = M10*M10 + M11*M11 + M12*M12;
        float s12 = M10*M20 + M11*M21 + M12*M22;
        float s22 = M20*M20 + M21*M21 + M22*M22;

        float lim = 1.3f * tanfov;
        float invz = 1.0f / t2;
        float txc = fminf(fmaxf(t0*invz, -lim), lim) * t2;
        float tyc = fminf(fmaxf(t1*invz, -lim), lim) * t2;
        float J00 = fx*invz,  J02 = -fx*txc*invz*invz;
        float J11 = fy*invz,  J12 = -fy*tyc*invz*invz;

        float T00 = J00*V[0] + J02*V[8];
        float T01 = J00*V[1] + J02*V[9];
        float T02 = J00*V[2] + J02*V[10];
        float T10 = J11*V[4] + J12*V[8];
        float T11 = J11*V[5] + J12*V[9];
        float T12 = J11*V[6] + J12*V[10];

        float u0 = s00*T00 + s01*T01 + s02*T02;
        float u1 = s01*T00 + s11*T01 + s12*T02;
        float u2 = s02*T00 + s12*T01 + s22*T02;
        float cov00 = T00*u0 + T01*u1 + T02*u2;
        float cov01 = T10*u0 + T11*u1 + T12*u2;
        float v0 = s00*T10 + s01*T11 + s02*T12;
        float v1 = s01*T10 + s11*T11 + s12*T12;
        float v2 = s02*T10 + s12*T11 + s22*T12;
        float cov11 = T10*v0 + T11*v1 + T12*v2;

        float a = cov00 + 0.3f;
        float b = cov01;
        float c = cov11 + 0.3f;
        float det = a*c - b*b;
        bool valid = (depth > 0.2f) && (det > 0.0f);
        float det_s = valid ? det : 1.0f;
        float invdet = 1.0f / det_s;
        float ca = c * invdet;
        float cbn = -b * invdet;
        float cc = a * invdet;

        float mid = 0.5f * (a + c);
        float lam = mid + sqrtf(fmaxf(mid*mid - det, 0.1f));
        float rad = valid ? ceilf(3.0f * sqrtf(lam)) : 0.0f;

        float op = ops[i];
        const float SH_C0 = 0.28209479177387814f;
        float cr  = fmaxf(SH_C0 * feats[3*i]   + 0.5f, 0.0f);
        float cg  = fmaxf(SH_C0 * feats[3*i+1] + 0.5f, 0.0f);
        float cbl = fmaxf(SH_C0 * feats[3*i+2] + 0.5f, 0.0f);

        // Exact cull bound: contribution nonzero iff Q <= 2*ln(255*op).
        float tau = logf(255.0f * op) + 0.02f;
        float dxm = sqrtf(fmaxf(2.0f * tau * a, 0.0f)) + 1.0f;
        float dym = sqrtf(fmaxf(2.0f * tau * c, 0.0f)) + 1.0f;

        float4 bb;
        if (valid) bb = make_float4(px - dxm, px + dxm, py - dym, py + dym);
        else       bb = make_float4(1e9f, -1e9f, 1e9f, -1e9f);

        g_PA[i]  = make_float4(px, py, ca, cbn);
        g_PB[i]  = make_float4(cc, op, cr, cg);
        g_Pcb[i] = cbl;
        g_PBB[i] = bb;
        float dkey = valid ? depth : __int_as_float(0x7f800000);
        g_key[i] = ((unsigned long long)__float_as_uint(dkey) << 32) | (unsigned)i;

        out_radii[i] = rad;
    }

    grid_barrier(0);

    // ================= Phase 2: rank sort + permute + tile masks ===========
    // stage all keys into shared
    for (int i = tid; i < NP; i += NT) s_keys[i] = g_key[i];
    __syncthreads();

    {
        int lane = tid & 31;
        int warp = tid >> 5;               // 4 warps, 4 gaussians each
        #pragma unroll
        for (int q = 0; q < 4; q++) {
            int i = blk * GPB + warp * 4 + q;
            unsigned long long mykey = s_keys[i];
            int cnt = 0;
            #pragma unroll 8
            for (int it = 0; it < NP / 32; it++)
                cnt += (s_keys[lane + 32 * it] < mykey) ? 1 : 0;
            int r = __reduce_add_sync(0xffffffffu, cnt);   // stable rank (keys unique)

            if (lane == 0) {
                g_SA[r]  = g_PA[i];
                g_SB[r]  = g_PB[i];
                g_Scb[r] = g_Pcb[i];

                float4 bb = g_PBB[i];
                int txl = max(0,       (int)floorf(bb.x * (1.0f / TW)));
                int txh = min(NTX - 1, (int)floorf(bb.y * (1.0f / TW)));
                int tyl = max(0,       (int)floorf(bb.z * (1.0f / TH)));
                int tyh = min(NTY - 1, (int)floorf(bb.w * (1.0f / TH)));
                unsigned bit = 1u << (r & 31);
                int wofs = r >> 5;
                for (int ty = tyl; ty <= tyh; ty++)
                    for (int tx = txl; tx <= txh; tx++)
                        atomicOr(&g_mask[(ty * NTX + tx) * MWORDS + wofs], bit);
            }
        }
    }

    grid_barrier(1);

    // ================= Phase 3: render tile blk ============================
    int x0 = (blk & (NTX - 1)) * TW;
    int y0 = (blk >> 3) * TH;
    int lx = tid & 15, ly = tid >> 4;
    float gx = (float)(x0 + lx);
    float gy = (float)(y0 + ly);

    if (tid < MWORDS) smask[tid] = g_mask[blk * MWORDS + tid];
    __syncthreads();

    if (tid < 32) {
        int c0 = __popc(smask[tid]);
        int c1 = __popc(smask[tid + 32]);
        int s0 = c0, s1 = c1;
        #pragma unroll
        for (int d = 1; d < 32; d <<= 1) {
            int t0 = __shfl_up_sync(0xffffffffu, s0, d);
            int t1 = __shfl_up_sync(0xffffffffu, s1, d);
            if (tid >= d) { s0 += t0; s1 += t1; }
        }
        int tot0 = __shfl_sync(0xffffffffu, s0, 31);
        sofs[tid]      = s0 - c0;
        sofs[tid + 32] = tot0 + s1 - c1;
        if (tid == 31) sofs[64] = tot0 + s1;
    }
    __syncthreads();

    int total = sofs[MWORDS];
    float T = 1.0f, C0 = 0.0f, C1 = 0.0f, C2 = 0.0f;
    const float ALPHA_MIN = 1.0f / 255.0f;

    for (int base = 0; base < total; base += LISTCAP) {
        int idx = base + tid;
        if (idx < total) {
            int lo = 0, hi = MWORDS - 1;
            #pragma unroll
            for (int step = 0; step < 6; step++) {
                int mid = (lo + hi + 1) >> 1;
                if (sofs[mid] <= idx) lo = mid; else hi = mid - 1;
            }
            int w = lo;
            int k = idx - sofs[w];
            unsigned mm = smask[w];
            int pos = 0;
            int c;
            c = __popc(mm & 0xFFFFu); if (k >= c) { k -= c; mm >>= 16; pos += 16; }
            c = __popc(mm & 0xFFu);   if (k >= c) { k -= c; mm >>= 8;  pos += 8; }
            c = __popc(mm & 0xFu);    if (k >= c) { k -= c; mm >>= 4;  pos += 4; }
            c = __popc(mm & 0x3u);    if (k >= c) { k -= c; mm >>= 2;  pos += 2; }
            c = __popc(mm & 0x1u);    if (k >= c) {         pos += 1; }
            int j = w * 32 + pos;
            lA[tid]  = g_SA[j];
            lB[tid]  = g_SB[j];
            lCb[tid] = g_Scb[j];
        }
        __syncthreads();

        int cnt = min(LISTCAP, total - base);
        if (T > 1e-5f) {
            for (int j = 0; j < cnt; j++) {
                float4 A = lA[j];
                float4 B = lB[j];
                float dx = gx - A.x, dy = gy - A.y;
                float q = fmaf(A.z * dx, dx, B.x * dy * dy);
                float power = fmaf(-0.5f, q, -A.w * dx * dy);
                if (power > 0.0f) continue;
                float alpha = fminf(0.99f, B.y * __expf(power));
                if (alpha < ALPHA_MIN) continue;
                float w = T * alpha;
                C0 = fmaf(w, B.z, C0);
                C1 = fmaf(w, B.w, C1);
                C2 = fmaf(w, lCb[j], C2);
                T *= (1.0f - alpha);
            }
        }
        if (base + LISTCAP < total) {
            if (__syncthreads_count(T > 1e-5f) == 0) break;
        }
    }

    int pix = (y0 + ly) * IMG + (x0 + lx);
    out[pix]          = C0 + T;
    out[NPIX + pix]   = C1 + T;
    out[2*NPIX + pix] = C2 + T;
}

extern "C" void kernel_launch(void* const* d_in, const int* in_sizes, int n_in,
                              void* d_out, int out_size)
{
    const float* means  = (const float*)d_in[0];
    const float* feats  = (const float*)d_in[2];
    const float* ops    = (const float*)d_in[3];
    const float* scales = (const float*)d_in[4];
    const float* rots   = (const float*)d_in[5];
    const float* V      = (const float*)d_in[6];
    const float* PM     = (const float*)d_in[7];

    fused_kernel<<<NB, NT>>>(means, feats, ops, scales, rots, V, PM, (float*)d_out);
}

// round 7
// speedup vs baseline: 1.0226x; 1.0226x over previous
#include <cuda_runtime.h>
#include <math.h>

#define NP 2048
#define IMG 128
#define NPIX (IMG*IMG)
#define TW 16
#define TH 8
#define NTX 8
#define NB 128          // one block per 16x8 tile
#define NT 256
#define GPT (NP/NT)     // 8 gaussians preprocessed per thread

struct SMem {
    unsigned long long key[NP];   // (depth_bits<<32)|orig_idx for survivors
    float4 A[NP];                 // px, py, conic_a, conic_b
    float4 B[NP];                 // conic_c, opacity, col_r, col_g
    float  Cb[NP];                // col_b
    int    perm[NP];              // rank -> list position
    float  V[16];
    float  PM[16];
    int    cnt;
};

extern __shared__ char smem_raw[];

__global__ __launch_bounds__(NT)
void fused_kernel(const float* __restrict__ means,
                  const float* __restrict__ feats,
                  const float* __restrict__ ops,
                  const float* __restrict__ scales,
                  const float* __restrict__ rots,
                  const float* __restrict__ Vg,
                  const float* __restrict__ PMg,
                  float* __restrict__ out)
{
    SMem* S = (SMem*)smem_raw;
    int tid = threadIdx.x;
    int blk = blockIdx.x;

    if (tid < 16) { S->V[tid] = Vg[tid]; S->PM[tid] = PMg[tid]; }
    if (tid == 0) S->cnt = 0;
    __syncthreads();

    const float* V  = S->V;
    const float* PM = S->PM;
    float* out_radii = out + 3 * NPIX;

    int x0 = (blk & (NTX - 1)) * TW;
    int y0 = (blk >> 3) * TH;
    float tx0 = (float)x0, tx1 = (float)(x0 + TW - 1);
    float ty0 = (float)y0, ty1 = (float)(y0 + TH - 1);

    const float tanfov = 0.57735026918962576f;
    const float fx = (float)IMG / (2.0f * tanfov);
    const float fy = fx;
    const float SH_C0 = 0.28209479177387814f;

    // ---- Phase 1: every block preprocesses ALL gaussians (8 per thread) ----
    #pragma unroll
    for (int k = 0; k < GPT; k++) {
        int i = tid + NT * k;

        float mx = means[3*i], my = means[3*i+1], mz = means[3*i+2];

        float t0 = V[0]*mx + V[1]*my + V[2]*mz + V[3];
        float t1 = V[4]*mx + V[5]*my + V[6]*mz + V[7];
        float t2 = V[8]*mx + V[9]*my + V[10]*mz + V[11];
        float depth = t2;

        float ph0 = PM[0]*mx + PM[1]*my + PM[2]*mz + PM[3];
        float ph1 = PM[4]*mx + PM[5]*my + PM[6]*mz + PM[7];
        float pw  = PM[12]*mx + PM[13]*my + PM[14]*mz + PM[15];
        float invpw = 1.0f / (pw + 1e-7f);
        float px = ((ph0*invpw + 1.0f) * (float)IMG - 1.0f) * 0.5f;
        float py = ((ph1*invpw + 1.0f) * (float)IMG - 1.0f) * 0.5f;

        float4 q4 = ((const float4*)rots)[i];
        float qw = q4.x, qx = q4.y, qy = q4.z, qz = q4.w;
        float qn = rsqrtf(qw*qw + qx*qx + qy*qy + qz*qz);
        qw *= qn; qx *= qn; qy *= qn; qz *= qn;
        float R00 = 1.0f - 2.0f*(qy*qy + qz*qz);
        float R01 = 2.0f*(qx*qy - qw*qz);
        float R02 = 2.0f*(qx*qz + qw*qy);
        float R10 = 2.0f*(qx*qy + qw*qz);
        float R11 = 1.0f - 2.0f*(qx*qx + qz*qz);
        float R12 = 2.0f*(qy*qz - qw*qx);
        float R20 = 2.0f*(qx*qz - qw*qy);
        float R21 = 2.0f*(qy*qz + qw*qx);
        float R22 = 1.0f - 2.0f*(qx*qx + qy*qy);

        float s0 = scales[3*i], s1 = scales[3*i+1], s2 = scales[3*i+2];
        float M00 = R00*s0, M01 = R01*s1, M02 = R02*s2;
        float M10 = R10*s0, M11 = R11*s1, M12 = R12*s2;
        float M20 = R20*s0, M21 = R21*s1, M22 = R22*s2;

        float s00 = M00*M00 + M01*M01 + M02*M02;
        float s01 = M00*M10 + M01*M11 + M02*M12;
        float s02 = M00*M20 + M01*M21 + M02*M22;
        float s11 = M10*M10 + M11*M11 + M12*M12;
        float s12 = M10*M20 + M11*M21 + M12*M22;
        float s22 = M20*M20 + M21*M21 + M22*M22;

        float lim = 1.3f * tanfov;
        float invz = 1.0f / t2;
        float txc = fminf(fmaxf(t0*invz, -lim), lim) * t2;
        float tyc = fminf(fmaxf(t1*invz, -lim), lim) * t2;
        float J00 = fx*invz,  J02 = -fx*txc*invz*invz;
        float J11 = fy*invz,  J12 = -fy*tyc*invz*invz;

        float T00 = J00*V[0] + J02*V[8];
        float T01 = J00*V[1] + J02*V[9];
        float T02 = J00*V[2] + J02*V[10];
        float T10 = J11*V[4] + J12*V[8];
        float T11 = J11*V[5] + J12*V[9];
        float T12 = J11*V[6] + J12*V[10];

        float u0 = s00*T00 + s01*T01 + s02*T02;
        float u1 = s01*T00 + s11*T01 + s12*T02;
        float u2 = s02*T00 + s12*T01 + s22*T02;
        float cov00 = T00*u0 + T01*u1 + T02*u2;
        float cov01 = T10*u0 + T11*u1 + T12*u2;
        float v0 = s00*T10 + s01*T11 + s02*T12;
        float v1 = s01*T10 + s11*T11 + s12*T12;
        float v2 = s02*T10 + s12*T11 + s22*T12;
        float cov11 = T10*v0 + T11*v1 + T12*v2;

        float a = cov00 + 0.3f;
        float b = cov01;
        float c = cov11 + 0.3f;
        float det = a*c - b*b;
        bool valid = (depth > 0.2f) && (det > 0.0f);
        float det_s = valid ? det : 1.0f;
        float invdet = 1.0f / det_s;
        float ca = c * invdet;
        float cbn = -b * invdet;
        float cc = a * invdet;

        // radii output: only the owning block writes gaussian i's radius
        if ((i >> 4) == blk) {
            float mid = 0.5f * (a + c);
            float lam = mid + sqrtf(fmaxf(mid*mid - det, 0.1f));
            out_radii[i] = valid ? ceilf(3.0f * sqrtf(lam)) : 0.0f;
        }

        if (valid) {
            float op = ops[i];
            // exact cull: contribution nonzero iff Q <= 2*ln(255*op)
            float tau = logf(255.0f * op) + 0.02f;
            float dxm = sqrtf(fmaxf(2.0f * tau * a, 0.0f)) + 1.0f;
            float dym = sqrtf(fmaxf(2.0f * tau * c, 0.0f)) + 1.0f;

            if (px - dxm <= tx1 && px + dxm >= tx0 &&
                py - dym <= ty1 && py + dym >= ty0) {
                float cr  = fmaxf(SH_C0 * feats[3*i]   + 0.5f, 0.0f);
                float cg  = fmaxf(SH_C0 * feats[3*i+1] + 0.5f, 0.0f);
                float cbl = fmaxf(SH_C0 * feats[3*i+2] + 0.5f, 0.0f);

                int pos = atomicAdd(&S->cnt, 1);
                S->key[pos] = ((unsigned long long)__float_as_uint(depth) << 32)
                              | (unsigned)i;
                S->A[pos]  = make_float4(px, py, ca, cbn);
                S->B[pos]  = make_float4(cc, op, cr, cg);
                S->Cb[pos] = cbl;
            }
        }
    }
    __syncthreads();

    int n = S->cnt;

    // ---- Phase 2: local stable rank sort (exact (depth, orig_idx) order) ----
    for (int e = tid; e < n; e += NT) {
        unsigned long long mk = S->key[e];
        int r = 0;
        for (int j = 0; j < n; j++) r += (S->key[j] < mk) ? 1 : 0;
        S->perm[r] = e;              // keys unique -> exact permutation
    }
    __syncthreads();

    // ---- Phase 3: blend (one pixel per thread, threads [0,128)) ----
    if (tid < TW * TH) {
        float gx = (float)(x0 + (tid & 15));
        float gy = (float)(y0 + (tid >> 4));
        float T = 1.0f, C0 = 0.0f, C1 = 0.0f, C2 = 0.0f;
        const float ALPHA_MIN = 1.0f / 255.0f;

        for (int j = 0; j < n; j++) {
            int p = S->perm[j];
            float4 A = S->A[p];
            float4 B = S->B[p];
            float dx = gx - A.x, dy = gy - A.y;
            float q = fmaf(A.z * dx, dx, B.x * dy * dy);
            float power = fmaf(-0.5f, q, -A.w * dx * dy);
            if (power > 0.0f) continue;
            float alpha = fminf(0.99f, B.y * __expf(power));
            if (alpha < ALPHA_MIN) continue;
            float w = T * alpha;
            C0 = fmaf(w, B.z, C0);
            C1 = fmaf(w, B.w, C1);
            C2 = fmaf(w, S->Cb[p], C2);
            T *= (1.0f - alpha);
            if (T < 1e-5f) break;
        }

        int pix = (y0 + (tid >> 4)) * IMG + x0 + (tid & 15);
        out[pix]          = C0 + T;
        out[NPIX + pix]   = C1 + T;
        out[2*NPIX + pix] = C2 + T;
    }
}

extern "C" void kernel_launch(void* const* d_in, const int* in_sizes, int n_in,
                              void* d_out, int out_size)
{
    const float* means  = (const float*)d_in[0];
    const float* feats  = (const float*)d_in[2];
    const float* ops    = (const float*)d_in[3];
    const float* scales = (const float*)d_in[4];
    const float* rots   = (const float*)d_in[5];
    const float* V      = (const float*)d_in[6];
    const float* PM     = (const float*)d_in[7];

    int smem_bytes = (int)sizeof(SMem);
    cudaFuncSetAttribute(fused_kernel,
                         cudaFuncAttributeMaxDynamicSharedMemorySize, smem_bytes);
    fused_kernel<<<NB, NT, smem_bytes>>>(means, feats, ops, scales, rots, V, PM,
                                         (float*)d_out);
}

// round 9
// speedup vs baseline: 1.4764x; 1.4437x over previous
#include <cuda_runtime.h>
#include <math.h>

#define NP 2048
#define IMG 128
#define NPIX (IMG*IMG)
#define TW 16
#define TH 8
#define NTX 8
#define NTY 16
#define NTILES (NTX*NTY)
#define MWORDS 64            // 2048 bits / 32
#define LISTCAP 128

// Sorted per-gaussian data (written by K1 at sorted rank)
__device__ float4 g_SA[NP];        // px, py, ha=-0.5*conic_a, hb=-conic_b
__device__ float4 g_SB[NP];        // hc=-0.5*conic_c, opacity, col_r, col_g
__device__ float  g_Scb[NP];       // col_b
// Per-tile bitmask over sorted ranks. Zero at load; each render block re-zeros
// its own slice after consuming it, so graph replays see clean masks.
__device__ unsigned g_mask[NTILES * MWORDS];

// ===========================================================================
// K1: depth keys (cheap: valid == depth>0.2 since det>0 always) + exact stable
// rank + full preprocess + ellipse-culled tile masks + radii.
// 128 blocks x 256 threads; warp w handles gaussians blk*16 + 2w, +1.
__global__ __launch_bounds__(256)
void prep_kernel(const float* __restrict__ means,
                 const float* __restrict__ feats,
                 const float* __restrict__ ops,
                 const float* __restrict__ scales,
                 const float* __restrict__ rots,
                 const float* __restrict__ V,
                 const float* __restrict__ PM,
                 float* __restrict__ out)
{
    __shared__ unsigned long long s_keys[NP];   // 16KB

    int tid  = threadIdx.x;
    int lane = tid & 31;
    int warp = tid >> 5;
    int blk  = blockIdx.x;
    float* out_radii = out + 3 * NPIX;

    // ---- stage depth keys for ALL gaussians (8 per thread) ----
    #pragma unroll
    for (int k = 0; k < NP / 256; k++) {
        int i = tid + 256 * k;
        float mx = means[3*i], my = means[3*i+1], mz = means[3*i+2];
        float t2 = V[8]*mx + V[9]*my + V[10]*mz + V[11];
        // det>0 always: cov2d is PSD, +0.3I makes det >= 0.09. valid == depth>0.2
        unsigned bits = (t2 > 0.2f) ? __float_as_uint(t2) : 0x7f800000u;
        s_keys[i] = ((unsigned long long)bits << 32) | (unsigned)i;
    }
    __syncthreads();

    const float tanfov = 0.57735026918962576f;
    const float fx = (float)IMG / (2.0f * tanfov);
    const float fy = fx;
    const float SH_C0 = 0.28209479177387814f;

    #pragma unroll
    for (int gq = 0; gq < 2; gq++) {
        int i = blk * 16 + warp * 2 + gq;

        // ---- exact stable rank (keys unique) ----
        unsigned long long mykey = s_keys[i];
        int cnt = 0;
        #pragma unroll 8
        for (int it = 0; it < NP / 32; it++)
            cnt += (s_keys[lane + 32 * it] < mykey) ? 1 : 0;
        int r = __reduce_add_sync(0xffffffffu, cnt);

        // ---- full preprocess (redundant across lanes, SIMT-uniform) ----
        float mx = means[3*i], my = means[3*i+1], mz = means[3*i+2];

        float t0 = V[0]*mx + V[1]*my + V[2]*mz + V[3];
        float t1 = V[4]*mx + V[5]*my + V[6]*mz + V[7];
        float t2 = V[8]*mx + V[9]*my + V[10]*mz + V[11];
        float depth = t2;

        float ph0 = PM[0]*mx + PM[1]*my + PM[2]*mz + PM[3];
        float ph1 = PM[4]*mx + PM[5]*my + PM[6]*mz + PM[7];
        float pw  = PM[12]*mx + PM[13]*my + PM[14]*mz + PM[15];
        float invpw = 1.0f / (pw + 1e-7f);
        float px = ((ph0*invpw + 1.0f) * (float)IMG - 1.0f) * 0.5f;
        float py = ((ph1*invpw + 1.0f) * (float)IMG - 1.0f) * 0.5f;

        float4 q4 = ((const float4*)rots)[i];
        float qw = q4.x, qx = q4.y, qy = q4.z, qz = q4.w;
        float qn = rsqrtf(qw*qw + qx*qx + qy*qy + qz*qz);
        qw *= qn; qx *= qn; qy *= qn; qz *= qn;
        float R00 = 1.0f - 2.0f*(qy*qy + qz*qz);
        float R01 = 2.0f*(qx*qy - qw*qz);
        float R02 = 2.0f*(qx*qz + qw*qy);
        float R10 = 2.0f*(qx*qy + qw*qz);
        float R11 = 1.0f - 2.0f*(qx*qx + qz*qz);
        float R12 = 2.0f*(qy*qz - qw*qx);
        float R20 = 2.0f*(qx*qz - qw*qy);
        float R21 = 2.0f*(qy*qz + qw*qx);
        float R22 = 1.0f - 2.0f*(qx*qx + qy*qy);

        float s0 = scales[3*i], s1 = scales[3*i+1], s2 = scales[3*i+2];
        float M00 = R00*s0, M01 = R01*s1, M02 = R02*s2;
        float M10 = R10*s0, M11 = R11*s1, M12 = R12*s2;
        float M20 = R20*s0, M21 = R21*s1, M22 = R22*s2;

        float s00 = M00*M00 + M01*M01 + M02*M02;
        float s01 = M00*M10 + M01*M11 + M02*M12;
        float s02 = M00*M20 + M01*M21 + M02*M22;
        float s11 = M10*M10 + M11*M11 + M12*M12;
        float s12 = M10*M20 + M11*M21 + M12*M22;
        float s22 = M20*M20 + M21*M21 + M22*M22;

        float lim = 1.3f * tanfov;
        float invz = 1.0f / t2;
        float txc = fminf(fmaxf(t0*invz, -lim), lim) * t2;
        float tyc = fminf(fmaxf(t1*invz, -lim), lim) * t2;
        float J00 = fx*invz,  J02 = -fx*txc*invz*invz;
        float J11 = fy*invz,  J12 = -fy*tyc*invz*invz;

        float T00 = J00*V[0] + J02*V[8];
        float T01 = J00*V[1] + J02*V[9];
        float T02 = J00*V[2] + J02*V[10];
        float T10 = J11*V[4] + J12*V[8];
        float T11 = J11*V[5] + J12*V[9];
        float T12 = J11*V[6] + J12*V[10];

        float u0 = s00*T00 + s01*T01 + s02*T02;
        float u1 = s01*T00 + s11*T01 + s12*T02;
        float u2 = s02*T00 + s12*T01 + s22*T02;
        float cov00 = T00*u0 + T01*u1 + T02*u2;
        float cov01 = T10*u0 + T11*u1 + T12*u2;
        float v0 = s00*T10 + s01*T11 + s02*T12;
        float v1 = s01*T10 + s11*T11 + s12*T12;
        float v2 = s02*T10 + s12*T11 + s22*T12;
        float cov11 = T10*v0 + T11*v1 + T12*v2;

        float a = cov00 + 0.3f;
        float b = cov01;
        float c = cov11 + 0.3f;
        float det = a*c - b*b;
        bool valid = (depth > 0.2f) && (det > 0.0f);
        float det_s = valid ? det : 1.0f;
        float invdet = 1.0f / det_s;
        float ca = c * invdet;
        float cbn = -b * invdet;
        float cc = a * invdet;

        float mid = 0.5f * (a + c);
        float lam = mid + sqrtf(fmaxf(mid*mid - det, 0.1f));   // >= lambda_max(cov)

        float op = ops[i];
        float cr  = fmaxf(SH_C0 * feats[3*i]   + 0.5f, 0.0f);
        float cg  = fmaxf(SH_C0 * feats[3*i+1] + 0.5f, 0.0f);
        float cbl = fmaxf(SH_C0 * feats[3*i+2] + 0.5f, 0.0f);

        if (lane == 0) {
            out_radii[i] = valid ? ceilf(3.0f * sqrtf(lam)) : 0.0f;
            // pre-negated conic for the blend loop
            g_SA[r]  = make_float4(px, py, -0.5f * ca, -cbn);
            g_SB[r]  = make_float4(-0.5f * cc, op, cr, cg);
            g_Scb[r] = cbl;
        }

        if (valid) {
            // exact cull: contribution nonzero iff Q <= 2*tau, tau = ln(255*op)
            float tau = logf(255.0f * op) + 0.02f;
            float dxm = sqrtf(fmaxf(2.0f * tau * a, 0.0f)) + 1.0f;
            float dym = sqrtf(fmaxf(2.0f * tau * c, 0.0f)) + 1.0f;
            int txl = max(0,       (int)floorf((px - dxm) * (1.0f / TW)));
            int txh = min(NTX - 1, (int)floorf((px + dxm) * (1.0f / TW)));
            int tyl = max(0,       (int)floorf((py - dym) * (1.0f / TH)));
            int tyh = min(NTY - 1, (int)floorf((py + dym) * (1.0f / TH)));

            if (txh >= txl && tyh >= tyl) {
                int bw = txh - txl + 1, bh = tyh - tyl + 1;
                int ntl = bw * bh;
                // Q(d) >= |d|^2 / lambda_max(cov)  (conic = cov^{-1}).
                // Safe cull: |d|^2 > 2*tau*lambda_max. lam >= lambda_max.
                float d2max = (2.0f * tau + 0.05f) * lam + 2.0f;
                unsigned bit = 1u << (r & 31);
                int wofs = r >> 5;
                for (int k = lane; k < ntl; k += 32) {
                    int tx = txl + (k % bw);
                    int ty = tyl + (k / bw);
                    float rx0 = (float)(tx * TW), rx1 = (float)(tx * TW + TW - 1);
                    float ry0 = (float)(ty * TH), ry1 = (float)(ty * TH + TH - 1);
                    float ddx = fmaxf(0.0f, fmaxf(rx0 - px, px - rx1));
                    float ddy = fmaxf(0.0f, fmaxf(ry0 - py, py - ry1));
                    if (ddx * ddx + ddy * ddy <= d2max)
                        atomicOr(&g_mask[(ty * NTX + tx) * MWORDS + wofs], bit);
                }
            }
        }
    }
}

// ===========================================================================
// K2: render one 16x8 tile per block from the rank bitmask.
__global__ __launch_bounds__(LISTCAP)
void render_kernel(float* __restrict__ out)
{
    int tid = threadIdx.x;
    int tile = blockIdx.x;
    int x0 = (tile & (NTX - 1)) * TW;
    int y0 = (tile >> 3) * TH;
    float gx = (float)(x0 + (tid & 15));
    float gy = (float)(y0 + (tid >> 4));

    __shared__ unsigned smask[MWORDS];
    __shared__ int sofs[MWORDS + 1];
    __shared__ float4 lA[LISTCAP], lB[LISTCAP];
    __shared__ float  lCb[LISTCAP];

    if (tid < MWORDS) smask[tid] = g_mask[tile * MWORDS + tid];
    __syncthreads();
    // re-zero our slice for the next graph replay (after everyone consumed it)
    if (tid < MWORDS) g_mask[tile * MWORDS + tid] = 0u;

    // warp 0: prefix-scan the 64 popcounts
    if (tid < 32) {
        int c0 = __popc(smask[tid]);
        int c1 = __popc(smask[tid + 32]);
        int s0 = c0, s1 = c1;
        #pragma unroll
        for (int d = 1; d < 32; d <<= 1) {
            int t0 = __shfl_up_sync(0xffffffffu, s0, d);
            int t1 = __shfl_up_sync(0xffffffffu, s1, d);
            if (tid >= d) { s0 += t0; s1 += t1; }
        }
        int tot0 = __shfl_sync(0xffffffffu, s0, 31);
        sofs[tid]      = s0 - c0;
        sofs[tid + 32] = tot0 + s1 - c1;
        if (tid == 31) sofs[64] = tot0 + s1;
    }
    __syncthreads();

    int total = sofs[MWORDS];
    float T = 1.0f, C0 = 0.0f, C1 = 0.0f, C2 = 0.0f;
    const float ALPHA_MIN = 1.0f / 255.0f;

    for (int base = 0; base < total; base += LISTCAP) {
        int idx = base + tid;
        if (idx < total) {
            int lo = 0, hi = MWORDS - 1;
            #pragma unroll
            for (int step = 0; step < 6; step++) {
                int mid = (lo + hi + 1) >> 1;
                if (sofs[mid] <= idx) lo = mid; else hi = mid - 1;
            }
            int w = lo;
            int k = idx - sofs[w];
            unsigned mm = smask[w];
            int pos = 0;
            int c;
            c = __popc(mm & 0xFFFFu); if (k >= c) { k -= c; mm >>= 16; pos += 16; }
            c = __popc(mm & 0xFFu);   if (k >= c) { k -= c; mm >>= 8;  pos += 8; }
            c = __popc(mm & 0xFu);    if (k >= c) { k -= c; mm >>= 4;  pos += 4; }
            c = __popc(mm & 0x3u);    if (k >= c) { k -= c; mm >>= 2;  pos += 2; }
            c = __popc(mm & 0x1u);    if (k >= c) {         pos += 1; }
            int j = w * 32 + pos;
            lA[tid]  = g_SA[j];
            lB[tid]  = g_SB[j];
            lCb[tid] = g_Scb[j];
        }
        __syncthreads();

        int cnt = min(LISTCAP, total - base);
        if (T > 1e-5f) {
            for (int j = 0; j < cnt; j++) {
                float4 A = lA[j];
                float4 B = lB[j];
                float dx = gx - A.x, dy = gy - A.y;
                // power = ha*dx^2 + hc*dy^2 + hb*dx*dy   (pre-negated terms)
                float power = fmaf(A.z * dx, dx, fmaf(B.x * dy, dy, A.w * dx * dy));
                if (power > 0.0f) continue;
                float alpha = fminf(0.99f, B.y * __expf(power));
                if (alpha < ALPHA_MIN) continue;
                float w = T * alpha;
                C0 = fmaf(w, B.z, C0);
                C1 = fmaf(w, B.w, C1);
                C2 = fmaf(w, lCb[j], C2);
                T *= (1.0f - alpha);
            }
        }
        if (base + LISTCAP < total) {
            if (__syncthreads_count(T > 1e-5f) == 0) break;
        }
    }

    int pix = (y0 + (tid >> 4)) * IMG + x0 + (tid & 15);
    out[pix]          = C0 + T;
    out[NPIX + pix]   = C1 + T;
    out[2*NPIX + pix] = C2 + T;
}

// ===========================================================================
extern "C" void kernel_launch(void* const* d_in, const int* in_sizes, int n_in,
                              void* d_out, int out_size)
{
    const float* means  = (const float*)d_in[0];
    const float* feats  = (const float*)d_in[2];
    const float* ops    = (const float*)d_in[3];
    const float* scales = (const float*)d_in[4];
    const float* rots   = (const float*)d_in[5];
    const float* V      = (const float*)d_in[6];
    const float* PM     = (const float*)d_in[7];

    float* out = (float*)d_out;

    prep_kernel<<<128, 256>>>(means, feats, ops, scales, rots, V, PM, out);
    render_kernel<<<NTILES, LISTCAP>>>(out);
}

// round 13
// speedup vs baseline: 2.9003x; 1.9645x over previous
#include <cuda_runtime.h>
#include <math.h>

#define NP 2048
#define IMG 128
#define NPIX (IMG*IMG)
#define TW 16
#define TH 8
#define NTX 8
#define NTY 16
#define NTILES (NTX*NTY)
#define MWORDS 64            // 2048 bits / 32
#define LISTCAP 512
#define SEGS 4
#define RT 512               // render threads: 4 segments x 128 pixels

// Sorted per-gaussian data (written by K1 at sorted rank)
__device__ float4 g_SA[NP];        // px, py, ha=-0.5*conic_a, hb=-conic_b
__device__ float4 g_SB[NP];        // hc=-0.5*conic_c, opacity, col_r, col_g
__device__ float  g_Scb[NP];       // col_b
// Per-tile bitmask over sorted ranks; render re-zeros its slice after reading.
__device__ unsigned g_mask[NTILES * MWORDS];

// ===========================================================================
// K1: cheap depth keys (valid == depth>0.2 since det>0 always) + exact stable
// rank + full preprocess + ellipse-culled tile masks + radii.
__global__ __launch_bounds__(256)
void prep_kernel(const float* __restrict__ means,
                 const float* __restrict__ feats,
                 const float* __restrict__ ops,
                 const float* __restrict__ scales,
                 const float* __restrict__ rots,
                 const float* __restrict__ V,
                 const float* __restrict__ PM,
                 float* __restrict__ out)
{
    __shared__ unsigned long long s_keys[NP];   // 16KB

    int tid  = threadIdx.x;
    int lane = tid & 31;
    int warp = tid >> 5;
    int blk  = blockIdx.x;
    float* out_radii = out + 3 * NPIX;

    #pragma unroll
    for (int k = 0; k < NP / 256; k++) {
        int i = tid + 256 * k;
        float mx = means[3*i], my = means[3*i+1], mz = means[3*i+2];
        float t2 = V[8]*mx + V[9]*my + V[10]*mz + V[11];
        unsigned bits = (t2 > 0.2f) ? __float_as_uint(t2) : 0x7f800000u;
        s_keys[i] = ((unsigned long long)bits << 32) | (unsigned)i;
    }
    __syncthreads();

    const float tanfov = 0.57735026918962576f;
    const float fx = (float)IMG / (2.0f * tanfov);
    const float fy = fx;
    const float SH_C0 = 0.28209479177387814f;

    #pragma unroll
    for (int gq = 0; gq < 2; gq++) {
        int i = blk * 16 + warp * 2 + gq;

        unsigned long long mykey = s_keys[i];
        int cnt = 0;
        #pragma unroll 8
        for (int it = 0; it < NP / 32; it++)
            cnt += (s_keys[lane + 32 * it] < mykey) ? 1 : 0;
        int r = __reduce_add_sync(0xffffffffu, cnt);

        float mx = means[3*i], my = means[3*i+1], mz = means[3*i+2];

        float t0 = V[0]*mx + V[1]*my + V[2]*mz + V[3];
        float t1 = V[4]*mx + V[5]*my + V[6]*mz + V[7];
        float t2 = V[8]*mx + V[9]*my + V[10]*mz + V[11];
        float depth = t2;

        float ph0 = PM[0]*mx + PM[1]*my + PM[2]*mz + PM[3];
        float ph1 = PM[4]*mx + PM[5]*my + PM[6]*mz + PM[7];
        float pw  = PM[12]*mx + PM[13]*my + PM[14]*mz + PM[15];
        float invpw = 1.0f / (pw + 1e-7f);
        float px = ((ph0*invpw + 1.0f) * (float)IMG - 1.0f) * 0.5f;
        float py = ((ph1*invpw + 1.0f) * (float)IMG - 1.0f) * 0.5f;

        float4 q4 = ((const float4*)rots)[i];
        float qw = q4.x, qx = q4.y, qy = q4.z, qz = q4.w;
        float qn = rsqrtf(qw*qw + qx*qx + qy*qy + qz*qz);
        qw *= qn; qx *= qn; qy *= qn; qz *= qn;
        float R00 = 1.0f - 2.0f*(qy*qy + qz*qz);
        float R01 = 2.0f*(qx*qy - qw*qz);
        float R02 = 2.0f*(qx*qz + qw*qy);
        float R10 = 2.0f*(qx*qy + qw*qz);
        float R11 = 1.0f - 2.0f*(qx*qx + qz*qz);
        float R12 = 2.0f*(qy*qz - qw*qx);
        float R20 = 2.0f*(qx*qz - qw*qy);
        float R21 = 2.0f*(qy*qz + qw*qx);
        float R22 = 1.0f - 2.0f*(qx*qx + qy*qy);

        float s0 = scales[3*i], s1 = scales[3*i+1], s2 = scales[3*i+2];
        float M00 = R00*s0, M01 = R01*s1, M02 = R02*s2;
        float M10 = R10*s0, M11 = R11*s1, M12 = R12*s2;
        float M20 = R20*s0, M21 = R21*s1, M22 = R22*s2;

        float s00 = M00*M00 + M01*M01 + M02*M02;
        float s01 = M00*M10 + M01*M11 + M02*M12;
        float s02 = M00*M20 + M01*M21 + M02*M22;
        float s11 = M10*M10 + M11*M11 + M12*M12;
        float s12 = M10*M20 + M11*M21 + M12*M22;
        float s22 = M20*M20 + M21*M21 + M22*M22;

        float lim = 1.3f * tanfov;
        float invz = 1.0f / t2;
        float txc = fminf(fmaxf(t0*invz, -lim), lim) * t2;
        float tyc = fminf(fmaxf(t1*invz, -lim), lim) * t2;
        float J00 = fx*invz,  J02 = -fx*txc*invz*invz;
        float J11 = fy*invz,  J12 = -fy*tyc*invz*invz;

        float T00 = J00*V[0] + J02*V[8];
        float T01 = J00*V[1] + J02*V[9];
        float T02 = J00*V[2] + J02*V[10];
        float T10 = J11*V[4] + J12*V[8];
        float T11 = J11*V[5] + J12*V[9];
        float T12 = J11*V[6] + J12*V[10];

        float u0 = s00*T00 + s01*T01 + s02*T02;
        float u1 = s01*T00 + s11*T01 + s12*T02;
        float u2 = s02*T00 + s12*T01 + s22*T02;
        float cov00 = T00*u0 + T01*u1 + T02*u2;
        float cov01 = T10*u0 + T11*u1 + T12*u2;
        float v0 = s00*T10 + s01*T11 + s02*T12;
        float v1 = s01*T10 + s11*T11 + s12*T12;
        float v2 = s02*T10 + s12*T11 + s22*T12;
        float cov11 = T10*v0 + T11*v1 + T12*v2;

        float a = cov00 + 0.3f;
        float b = cov01;
        float c = cov11 + 0.3f;
        float det = a*c - b*b;
        bool valid = (depth > 0.2f) && (det > 0.0f);
        float det_s = valid ? det : 1.0f;
        float invdet = 1.0f / det_s;
        float ca = c * invdet;
        float cbn = -b * invdet;
        float cc = a * invdet;

        float mid = 0.5f * (a + c);
        float lam = mid + sqrtf(fmaxf(mid*mid - det, 0.1f));   // >= lambda_max(cov)

        float op = ops[i];
        float cr  = fmaxf(SH_C0 * feats[3*i]   + 0.5f, 0.0f);
        float cg  = fmaxf(SH_C0 * feats[3*i+1] + 0.5f, 0.0f);
        float cbl = fmaxf(SH_C0 * feats[3*i+2] + 0.5f, 0.0f);

        if (lane == 0) {
            out_radii[i] = valid ? ceilf(3.0f * sqrtf(lam)) : 0.0f;
            g_SA[r]  = make_float4(px, py, -0.5f * ca, -cbn);
            g_SB[r]  = make_float4(-0.5f * cc, op, cr, cg);
            g_Scb[r] = cbl;
        }

        if (valid) {
            float tau = logf(255.0f * op) + 0.02f;
            float dxm = sqrtf(fmaxf(2.0f * tau * a, 0.0f)) + 1.0f;
            float dym = sqrtf(fmaxf(2.0f * tau * c, 0.0f)) + 1.0f;
            int txl = max(0,       (int)floorf((px - dxm) * (1.0f / TW)));
            int txh = min(NTX - 1, (int)floorf((px + dxm) * (1.0f / TW)));
            int tyl = max(0,       (int)floorf((py - dym) * (1.0f / TH)));
            int tyh = min(NTY - 1, (int)floorf((py + dym) * (1.0f / TH)));

            if (txh >= txl && tyh >= tyl) {
                int bw = txh - txl + 1, bh = tyh - tyl + 1;
                int ntl = bw * bh;
                // Q(d) >= |d|^2 / lambda_max(cov); safe cull if |d|^2 > 2*tau*lam
                float d2max = (2.0f * tau + 0.05f) * lam + 2.0f;
                unsigned bit = 1u << (r & 31);
                int wofs = r >> 5;
                for (int k = lane; k < ntl; k += 32) {
                    int tx = txl + (k % bw);
                    int ty = tyl + (k / bw);
                    float rx0 = (float)(tx * TW), rx1 = (float)(tx * TW + TW - 1);
                    float ry0 = (float)(ty * TH), ry1 = (float)(ty * TH + TH - 1);
                    float ddx = fmaxf(0.0f, fmaxf(rx0 - px, px - rx1));
                    float ddy = fmaxf(0.0f, fmaxf(ry0 - py, py - ry1));
                    if (ddx * ddx + ddy * ddy <= d2max)
                        atomicOr(&g_mask[(ty * NTX + tx) * MWORDS + wofs], bit);
                }
            }
        }
    }
}

// ===========================================================================
// K2: render one 16x8 tile per block. 512 threads = 4 list-segments x 128 px.
// Alpha blending is associative under (C,T)∘(C',T') = (C + T·C', T·T'),
// so segments run in parallel and compose in order.
__global__ __launch_bounds__(RT)
void render_kernel(float* __restrict__ out)
{
    int tid  = threadIdx.x;
    int seg  = tid >> 7;          // 0..3
    int pix  = tid & 127;
    int tile = blockIdx.x;
    int x0 = (tile & (NTX - 1)) * TW;
    int y0 = (tile >> 3) * TH;
    float gx = (float)(x0 + (pix & 15));
    float gy = (float)(y0 + (pix >> 4));

    __shared__ unsigned smask[MWORDS];
    __shared__ int sofs[MWORDS + 1];
    __shared__ float4 lA[LISTCAP], lB[LISTCAP];
    __shared__ float  lCb[LISTCAP];
    __shared__ float  pC0[SEGS][128], pC1[SEGS][128], pC2[SEGS][128], pT[SEGS][128];
    __shared__ float  runT[128];   // prefix transmittance broadcast

    if (tid < MWORDS) smask[tid] = g_mask[tile * MWORDS + tid];
    if (tid < 128) runT[tid] = 1.0f;
    __syncthreads();
    if (tid < MWORDS) g_mask[tile * MWORDS + tid] = 0u;   // replay-safe re-zero

    if (tid < 32) {
        int c0 = __popc(smask[tid]);
        int c1 = __popc(smask[tid + 32]);
        int s0 = c0, s1 = c1;
        #pragma unroll
        for (int d = 1; d < 32; d <<= 1) {
            int t0 = __shfl_up_sync(0xffffffffu, s0, d);
            int t1 = __shfl_up_sync(0xffffffffu, s1, d);
            if (tid >= d) { s0 += t0; s1 += t1; }
        }
        int tot0 = __shfl_sync(0xffffffffu, s0, 31);
        sofs[tid]      = s0 - c0;
        sofs[tid + 32] = tot0 + s1 - c1;
        if (tid == 31) sofs[64] = tot0 + s1;
    }
    __syncthreads();

    int total = sofs[MWORDS];
    const float ALPHA_MIN = 1.0f / 255.0f;

    // per-pixel running composition, owned by seg-0 threads
    float RC0 = 0.0f, RC1 = 0.0f, RC2 = 0.0f, RT_ = 1.0f;

    for (int base = 0; base < total; base += LISTCAP) {
        int idx = base + tid;
        if (idx < total) {
            int lo = 0, hi = MWORDS - 1;
            #pragma unroll
            for (int step = 0; step < 6; step++) {
                int mid = (lo + hi + 1) >> 1;
                if (sofs[mid] <= idx) lo = mid; else hi = mid - 1;
            }
            int w = lo;
            int k = idx - sofs[w];
            unsigned mm = smask[w];
            int pos = 0;
            int c;
            c = __popc(mm & 0xFFFFu); if (k >= c) { k -= c; mm >>= 16; pos += 16; }
            c = __popc(mm & 0xFFu);   if (k >= c) { k -= c; mm >>= 8;  pos += 8; }
            c = __popc(mm & 0xFu);    if (k >= c) { k -= c; mm >>= 4;  pos += 4; }
            c = __popc(mm & 0x3u);    if (k >= c) { k -= c; mm >>= 2;  pos += 2; }
            c = __popc(mm & 0x1u);    if (k >= c) {         pos += 1; }
            int j = w * 32 + pos;
            lA[tid]  = g_SA[j];
            lB[tid]  = g_SB[j];
            lCb[tid] = g_Scb[j];
        }
        __syncthreads();

        int cnt = min(LISTCAP, total - base);
        int q  = (cnt + SEGS - 1) / SEGS;
        int j0 = seg * q;
        int j1 = min(cnt, j0 + q);

        float c0 = 0.0f, c1 = 0.0f, c2 = 0.0f, t = 1.0f;
        if (runT[pix] > 1e-5f) {
            for (int j = j0; j < j1; j++) {
                float4 A = lA[j];
                float4 B = lB[j];
                float dx = gx - A.x, dy = gy - A.y;
                float power = fmaf(A.z * dx, dx, fmaf(B.x * dy, dy, A.w * dx * dy));
                if (power > 0.0f) continue;
                float alpha = fminf(0.99f, B.y * __expf(power));
                if (alpha < ALPHA_MIN) continue;
                float w = t * alpha;
                c0 = fmaf(w, B.z, c0);
                c1 = fmaf(w, B.w, c1);
                c2 = fmaf(w, lCb[j], c2);
                t *= (1.0f - alpha);
            }
        }
        pC0[seg][pix] = c0; pC1[seg][pix] = c1; pC2[seg][pix] = c2; pT[seg][pix] = t;
        __syncthreads();

        if (seg == 0) {
            #pragma unroll
            for (int s = 0; s < SEGS; s++) {
                RC0 = fmaf(RT_, pC0[s][pix], RC0);
                RC1 = fmaf(RT_, pC1[s][pix], RC1);
                RC2 = fmaf(RT_, pC2[s][pix], RC2);
                RT_ *= pT[s][pix];
            }
            runT[pix] = RT_;
        }
        // barrier doubles as early-exit vote (protects lA overwrite + runT)
        if (__syncthreads_count((seg == 0) ? (RT_ > 1e-5f) : 0) == 0 && seg != 99) {
            if (base + LISTCAP < total) break; else break;
        }
    }

    if (seg == 0) {
        int p = (y0 + (pix >> 4)) * IMG + x0 + (pix & 15);
        out[p]          = RC0 + RT_;
        out[NPIX + p]   = RC1 + RT_;
        out[2*NPIX + p] = RC2 + RT_;
    }
}

// ===========================================================================
extern "C" void kernel_launch(void* const* d_in, const int* in_sizes, int n_in,
                              void* d_out, int out_size)
{
    const float* means  = (const float*)d_in[0];
    const float* feats  = (const float*)d_in[2];
    const float* ops    = (const float*)d_in[3];
    const float* scales = (const float*)d_in[4];
    const float* rots   = (const float*)d_in[5];
    const float* V      = (const float*)d_in[6];
    const float* PM     = (const float*)d_in[7];

    float* out = (float*)d_out;

    prep_kernel<<<128, 256>>>(means, feats, ops, scales, rots, V, PM, out);
    render_kernel<<<NTILES, RT>>>(out);
}

// round 15
// speedup vs baseline: 2.9757x; 1.0260x over previous
#include <cuda_runtime.h>
#include <math.h>

#define NP 2048
#define IMG 128
#define NPIX (IMG*IMG)
#define TW 16
#define TH 8
#define NTX 8
#define NTY 16
#define NTILES (NTX*NTY)
#define MWORDS 64            // 2048 bits / 32
#define LISTCAP 512
#define SEGS 8
#define RT 1024              // render threads: 8 segments x 128 pixels

// Sorted per-gaussian data (written by K1 at sorted rank)
__device__ float4 g_SA[NP];        // px, py, ha=-0.5*conic_a, hb=-conic_b
__device__ float4 g_SB[NP];        // hc=-0.5*conic_c, opacity, col_r, col_g
__device__ float  g_Scb[NP];       // col_b
// Per-tile bitmask over sorted ranks; render re-zeros its slice after reading.
__device__ unsigned g_mask[NTILES * MWORDS];

// ===========================================================================
// K1: cheap depth keys (valid == depth>0.2 since det>0 always) + exact stable
// rank + full preprocess + ellipse-culled tile masks + radii.
__global__ __launch_bounds__(256)
void prep_kernel(const float* __restrict__ means,
                 const float* __restrict__ feats,
                 const float* __restrict__ ops,
                 const float* __restrict__ scales,
                 const float* __restrict__ rots,
                 const float* __restrict__ V,
                 const float* __restrict__ PM,
                 float* __restrict__ out)
{
    __shared__ unsigned long long s_keys[NP];   // 16KB

    int tid  = threadIdx.x;
    int lane = tid & 31;
    int warp = tid >> 5;
    int blk  = blockIdx.x;
    float* out_radii = out + 3 * NPIX;

    #pragma unroll
    for (int k = 0; k < NP / 256; k++) {
        int i = tid + 256 * k;
        float mx = means[3*i], my = means[3*i+1], mz = means[3*i+2];
        float t2 = V[8]*mx + V[9]*my + V[10]*mz + V[11];
        unsigned bits = (t2 > 0.2f) ? __float_as_uint(t2) : 0x7f800000u;
        s_keys[i] = ((unsigned long long)bits << 32) | (unsigned)i;
    }
    __syncthreads();

    const float tanfov = 0.57735026918962576f;
    const float fx = (float)IMG / (2.0f * tanfov);
    const float fy = fx;
    const float SH_C0 = 0.28209479177387814f;

    #pragma unroll
    for (int gq = 0; gq < 2; gq++) {
        int i = blk * 16 + warp * 2 + gq;

        unsigned long long mykey = s_keys[i];
        int cnt = 0;
        #pragma unroll 8
        for (int it = 0; it < NP / 32; it++)
            cnt += (s_keys[lane + 32 * it] < mykey) ? 1 : 0;
        int r = __reduce_add_sync(0xffffffffu, cnt);

        float mx = means[3*i], my = means[3*i+1], mz = means[3*i+2];

        float t0 = V[0]*mx + V[1]*my + V[2]*mz + V[3];
        float t1 = V[4]*mx + V[5]*my + V[6]*mz + V[7];
        float t2 = V[8]*mx + V[9]*my + V[10]*mz + V[11];
        float depth = t2;

        float ph0 = PM[0]*mx + PM[1]*my + PM[2]*mz + PM[3];
        float ph1 = PM[4]*mx + PM[5]*my + PM[6]*mz + PM[7];
        float pw  = PM[12]*mx + PM[13]*my + PM[14]*mz + PM[15];
        float invpw = 1.0f / (pw + 1e-7f);
        float px = ((ph0*invpw + 1.0f) * (float)IMG - 1.0f) * 0.5f;
        float py = ((ph1*invpw + 1.0f) * (float)IMG - 1.0f) * 0.5f;

        float4 q4 = ((const float4*)rots)[i];
        float qw = q4.x, qx = q4.y, qy = q4.z, qz = q4.w;
        float qn = rsqrtf(qw*qw + qx*qx + qy*qy + qz*qz);
        qw *= qn; qx *= qn; qy *= qn; qz *= qn;
        float R00 = 1.0f - 2.0f*(qy*qy + qz*qz);
        float R01 = 2.0f*(qx*qy - qw*qz);
        float R02 = 2.0f*(qx*qz + qw*qy);
        float R10 = 2.0f*(qx*qy + qw*qz);
        float R11 = 1.0f - 2.0f*(qx*qx + qz*qz);
        float R12 = 2.0f*(qy*qz - qw*qx);
        float R20 = 2.0f*(qx*qz - qw*qy);
        float R21 = 2.0f*(qy*qz + qw*qx);
        float R22 = 1.0f - 2.0f*(qx*qx + qy*qy);

        float s0 = scales[3*i], s1 = scales[3*i+1], s2 = scales[3*i+2];
        float M00 = R00*s0, M01 = R01*s1, M02 = R02*s2;
        float M10 = R10*s0, M11 = R11*s1, M12 = R12*s2;
        float M20 = R20*s0, M21 = R21*s1, M22 = R22*s2;

        float s00 = M00*M00 + M01*M01 + M02*M02;
        float s01 = M00*M10 + M01*M11 + M02*M12;
        float s02 = M00*M20 + M01*M21 + M02*M22;
        float s11 = M10*M10 + M11*M11 + M12*M12;
        float s12 = M10*M20 + M11*M21 + M12*M22;
        float s22 = M20*M20 + M21*M21 + M22*M22;

        float lim = 1.3f * tanfov;
        float invz = 1.0f / t2;
        float txc = fminf(fmaxf(t0*invz, -lim), lim) * t2;
        float tyc = fminf(fmaxf(t1*invz, -lim), lim) * t2;
        float J00 = fx*invz,  J02 = -fx*txc*invz*invz;
        float J11 = fy*invz,  J12 = -fy*tyc*invz*invz;

        float T00 = J00*V[0] + J02*V[8];
        float T01 = J00*V[1] + J02*V[9];
        float T02 = J00*V[2] + J02*V[10];
        float T10 = J11*V[4] + J12*V[8];
        float T11 = J11*V[5] + J12*V[9];
        float T12 = J11*V[6] + J12*V[10];

        float u0 = s00*T00 + s01*T01 + s02*T02;
        float u1 = s01*T00 + s11*T01 + s12*T02;
        float u2 = s02*T00 + s12*T01 + s22*T02;
        float cov00 = T00*u0 + T01*u1 + T02*u2;
        float cov01 = T10*u0 + T11*u1 + T12*u2;
        float v0 = s00*T10 + s01*T11 + s02*T12;
        float v1 = s01*T10 + s11*T11 + s12*T12;
        float v2 = s02*T10 + s12*T11 + s22*T12;
        float cov11 = T10*v0 + T11*v1 + T12*v2;

        float a = cov00 + 0.3f;
        float b = cov01;
        float c = cov11 + 0.3f;
        float det = a*c - b*b;
        bool valid = (depth > 0.2f) && (det > 0.0f);
        float det_s = valid ? det : 1.0f;
        float invdet = 1.0f / det_s;
        float ca = c * invdet;
        float cbn = -b * invdet;
        float cc = a * invdet;

        float mid = 0.5f * (a + c);
        float lam = mid + sqrtf(fmaxf(mid*mid - det, 0.1f));   // >= lambda_max(cov)

        float op = ops[i];
        float cr  = fmaxf(SH_C0 * feats[3*i]   + 0.5f, 0.0f);
        float cg  = fmaxf(SH_C0 * feats[3*i+1] + 0.5f, 0.0f);
        float cbl = fmaxf(SH_C0 * feats[3*i+2] + 0.5f, 0.0f);

        if (lane == 0) {
            out_radii[i] = valid ? ceilf(3.0f * sqrtf(lam)) : 0.0f;
            g_SA[r]  = make_float4(px, py, -0.5f * ca, -cbn);
            g_SB[r]  = make_float4(-0.5f * cc, op, cr, cg);
            g_Scb[r] = cbl;
        }

        if (valid) {
            float tau = logf(255.0f * op) + 0.02f;
            float dxm = sqrtf(fmaxf(2.0f * tau * a, 0.0f)) + 1.0f;
            float dym = sqrtf(fmaxf(2.0f * tau * c, 0.0f)) + 1.0f;
            int txl = max(0,       (int)floorf((px - dxm) * (1.0f / TW)));
            int txh = min(NTX - 1, (int)floorf((px + dxm) * (1.0f / TW)));
            int tyl = max(0,       (int)floorf((py - dym) * (1.0f / TH)));
            int tyh = min(NTY - 1, (int)floorf((py + dym) * (1.0f / TH)));

            if (txh >= txl && tyh >= tyl) {
                int bw = txh - txl + 1, bh = tyh - tyl + 1;
                int ntl = bw * bh;
                // Q(d) >= |d|^2 / lambda_max(cov); safe cull if |d|^2 > 2*tau*lam
                float d2max = (2.0f * tau + 0.05f) * lam + 2.0f;
                unsigned bit = 1u << (r & 31);
                int wofs = r >> 5;
                for (int k = lane; k < ntl; k += 32) {
                    int tx = txl + (k % bw);
                    int ty = tyl + (k / bw);
                    float rx0 = (float)(tx * TW), rx1 = (float)(tx * TW + TW - 1);
                    float ry0 = (float)(ty * TH), ry1 = (float)(ty * TH + TH - 1);
                    float ddx = fmaxf(0.0f, fmaxf(rx0 - px, px - rx1));
                    float ddy = fmaxf(0.0f, fmaxf(ry0 - py, py - ry1));
                    if (ddx * ddx + ddy * ddy <= d2max)
                        atomicOr(&g_mask[(ty * NTX + tx) * MWORDS + wofs], bit);
                }
            }
        }
    }
}

// ===========================================================================
// K2: render one 16x8 tile per block. 1024 threads = 8 list-segments x 128 px.
// Alpha blending composes associatively: (C,T)∘(C',T') = (C + T·C', T·T').
__global__ __launch_bounds__(RT)
void render_kernel(float* __restrict__ out)
{
    int tid  = threadIdx.x;
    int seg  = tid >> 7;          // 0..7
    int pix  = tid & 127;
    int tile = blockIdx.x;
    int x0 = (tile & (NTX - 1)) * TW;
    int y0 = (tile >> 3) * TH;
    float gx = (float)(x0 + (pix & 15));
    float gy = (float)(y0 + (pix >> 4));

    __shared__ unsigned smask[MWORDS];
    __shared__ int sofs[MWORDS + 1];
    __shared__ float4 lA[LISTCAP], lB[LISTCAP];
    __shared__ float  lCb[LISTCAP];
    __shared__ float  pC0[SEGS][128], pC1[SEGS][128], pC2[SEGS][128], pT[SEGS][128];
    __shared__ float  runT[128];   // prefix transmittance broadcast

    if (tid < MWORDS) smask[tid] = g_mask[tile * MWORDS + tid];
    if (tid < 128) runT[tid] = 1.0f;
    __syncthreads();
    if (tid < MWORDS) g_mask[tile * MWORDS + tid] = 0u;   // replay-safe re-zero

    if (tid < 32) {
        int c0 = __popc(smask[tid]);
        int c1 = __popc(smask[tid + 32]);
        int s0 = c0, s1 = c1;
        #pragma unroll
        for (int d = 1; d < 32; d <<= 1) {
            int t0 = __shfl_up_sync(0xffffffffu, s0, d);
            int t1 = __shfl_up_sync(0xffffffffu, s1, d);
            if (tid >= d) { s0 += t0; s1 += t1; }
        }
        int tot0 = __shfl_sync(0xffffffffu, s0, 31);
        sofs[tid]      = s0 - c0;
        sofs[tid + 32] = tot0 + s1 - c1;
        if (tid == 31) sofs[64] = tot0 + s1;
    }
    __syncthreads();

    int total = sofs[MWORDS];
    const float ALPHA_MIN = 1.0f / 255.0f;

    // per-pixel running composition, owned by seg-0 threads
    float RC0 = 0.0f, RC1 = 0.0f, RC2 = 0.0f, RT_ = 1.0f;

    for (int base = 0; base < total; base += LISTCAP) {
        int idx = base + tid;
        if (tid < LISTCAP && idx < total) {
            int lo = 0, hi = MWORDS - 1;
            #pragma unroll
            for (int step = 0; step < 6; step++) {
                int mid = (lo + hi + 1) >> 1;
                if (sofs[mid] <= idx) lo = mid; else hi = mid - 1;
            }
            int w = lo;
            int k = idx - sofs[w];
            unsigned mm = smask[w];
            int pos = 0;
            int c;
            c = __popc(mm & 0xFFFFu); if (k >= c) { k -= c; mm >>= 16; pos += 16; }
            c = __popc(mm & 0xFFu);   if (k >= c) { k -= c; mm >>= 8;  pos += 8; }
            c = __popc(mm & 0xFu);    if (k >= c) { k -= c; mm >>= 4;  pos += 4; }
            c = __popc(mm & 0x3u);    if (k >= c) { k -= c; mm >>= 2;  pos += 2; }
            c = __popc(mm & 0x1u);    if (k >= c) {         pos += 1; }
            int j = w * 32 + pos;
            lA[tid]  = g_SA[j];
            lB[tid]  = g_SB[j];
            lCb[tid] = g_Scb[j];
        }
        __syncthreads();

        int cnt = min(LISTCAP, total - base);
        int q  = (cnt + SEGS - 1) / SEGS;
        int j0 = min(cnt, seg * q);
        int j1 = min(cnt, j0 + q);

        float c0 = 0.0f, c1 = 0.0f, c2 = 0.0f, t = 1.0f;
        if (runT[pix] > 1e-5f) {
            for (int j = j0; j < j1; j++) {
                float4 A = lA[j];
                float4 B = lB[j];
                float dx = gx - A.x, dy = gy - A.y;
                float power = fmaf(A.z * dx, dx, fmaf(B.x * dy, dy, A.w * dx * dy));
                if (power > 0.0f) continue;
                float alpha = fminf(0.99f, B.y * __expf(power));
                if (alpha < ALPHA_MIN) continue;
                float w = t * alpha;
                c0 = fmaf(w, B.z, c0);
                c1 = fmaf(w, B.w, c1);
                c2 = fmaf(w, lCb[j], c2);
                t *= (1.0f - alpha);
            }
        }
        pC0[seg][pix] = c0; pC1[seg][pix] = c1; pC2[seg][pix] = c2; pT[seg][pix] = t;
        __syncthreads();

        if (seg == 0) {
            #pragma unroll
            for (int s = 0; s < SEGS; s++) {
                RC0 = fmaf(RT_, pC0[s][pix], RC0);
                RC1 = fmaf(RT_, pC1[s][pix], RC1);
                RC2 = fmaf(RT_, pC2[s][pix], RC2);
                RT_ *= pT[s][pix];
            }
            runT[pix] = RT_;
        }
        // barrier doubles as early-exit vote (protects lA overwrite + runT)
        int alive = __syncthreads_count((seg == 0) ? (RT_ > 1e-5f) : 0);
        if (alive == 0) break;
    }

    if (seg == 0) {
        int p = (y0 + (pix >> 4)) * IMG + x0 + (pix & 15);
        out[p]          = RC0 + RT_;
        out[NPIX + p]   = RC1 + RT_;
        out[2*NPIX + p] = RC2 + RT_;
    }
}

// ===========================================================================
extern "C" void kernel_launch(void* const* d_in, const int* in_sizes, int n_in,
                              void* d_out, int out_size)
{
    const float* means  = (const float*)d_in[0];
    const float* feats  = (const float*)d_in[2];
    const float* ops    = (const float*)d_in[3];
    const float* scales = (const float*)d_in[4];
    const float* rots   = (const float*)d_in[5];
    const float* V      = (const float*)d_in[6];
    const float* PM     = (const float*)d_in[7];

    float* out = (float*)d_out;

    prep_kernel<<<128, 256>>>(means, feats, ops, scales, rots, V, PM, out);
    render_kernel<<<NTILES, RT>>>(out);
}

// round 17
// speedup vs baseline: 3.2519x; 1.0928x over previous
#include <cuda_runtime.h>
#include <math.h>

#define NP 2048
#define IMG 128
#define TW 16
#define TH 8
#define NTX 8
#define NTY 16
#define NTILES (NTX*NTY)
#define NPIX (IMG*IMG)
#define MWORDS 64            // 2048 bits / 32
#define LISTCAP 1024
#define SEGS 8
#define RT 1024              // render threads: 8 segments x 128 pixels

// Sorted per-gaussian data (written by K1 at sorted rank)
__device__ float4 g_SA[NP];        // px, py, ha=-0.5*conic_a, hb=-conic_b
__device__ float4 g_SB[NP];        // hc=-0.5*conic_c, opacity, col_r, col_g
__device__ float  g_Scb[NP];       // col_b
// Per-tile bitmask over sorted ranks; render re-zeros its slice after reading.
__device__ unsigned g_mask[NTILES * MWORDS];

// ===========================================================================
// K1: cheap depth keys (valid == depth>0.2 since det>0 always) + exact stable
// rank + full preprocess + exact-ellipse-culled tile masks + radii.
__global__ __launch_bounds__(256)
void prep_kernel(const float* __restrict__ means,
                 const float* __restrict__ feats,
                 const float* __restrict__ ops,
                 const float* __restrict__ scales,
                 const float* __restrict__ rots,
                 const float* __restrict__ V,
                 const float* __restrict__ PM,
                 float* __restrict__ out)
{
    __shared__ unsigned long long s_keys[NP];   // 16KB

    int tid  = threadIdx.x;
    int lane = tid & 31;
    int warp = tid >> 5;
    int blk  = blockIdx.x;
    float* out_radii = out + 3 * NPIX;

    #pragma unroll
    for (int k = 0; k < NP / 256; k++) {
        int i = tid + 256 * k;
        float mx = means[3*i], my = means[3*i+1], mz = means[3*i+2];
        float t2 = V[8]*mx + V[9]*my + V[10]*mz + V[11];
        unsigned bits = (t2 > 0.2f) ? __float_as_uint(t2) : 0x7f800000u;
        s_keys[i] = ((unsigned long long)bits << 32) | (unsigned)i;
    }
    __syncthreads();

    const float tanfov = 0.57735026918962576f;
    const float fx = (float)IMG / (2.0f * tanfov);
    const float fy = fx;
    const float SH_C0 = 0.28209479177387814f;

    #pragma unroll
    for (int gq = 0; gq < 2; gq++) {
        int i = blk * 16 + warp * 2 + gq;

        unsigned long long mykey = s_keys[i];
        int cnt = 0;
        #pragma unroll 8
        for (int it = 0; it < NP / 32; it++)
            cnt += (s_keys[lane + 32 * it] < mykey) ? 1 : 0;
        int r = __reduce_add_sync(0xffffffffu, cnt);

        float mx = means[3*i], my = means[3*i+1], mz = means[3*i+2];

        float t0 = V[0]*mx + V[1]*my + V[2]*mz + V[3];
        float t1 = V[4]*mx + V[5]*my + V[6]*mz + V[7];
        float t2 = V[8]*mx + V[9]*my + V[10]*mz + V[11];
        float depth = t2;

        float ph0 = PM[0]*mx + PM[1]*my + PM[2]*mz + PM[3];
        float ph1 = PM[4]*mx + PM[5]*my + PM[6]*mz + PM[7];
        float pw  = PM[12]*mx + PM[13]*my + PM[14]*mz + PM[15];
        float invpw = 1.0f / (pw + 1e-7f);
        float px = ((ph0*invpw + 1.0f) * (float)IMG - 1.0f) * 0.5f;
        float py = ((ph1*invpw + 1.0f) * (float)IMG - 1.0f) * 0.5f;

        float4 q4 = ((const float4*)rots)[i];
        float qw = q4.x, qx = q4.y, qy = q4.z, qz = q4.w;
        float qn = rsqrtf(qw*qw + qx*qx + qy*qy + qz*qz);
        qw *= qn; qx *= qn; qy *= qn; qz *= qn;
        float R00 = 1.0f - 2.0f*(qy*qy + qz*qz);
        float R01 = 2.0f*(qx*qy - qw*qz);
        float R02 = 2.0f*(qx*qz + qw*qy);
        float R10 = 2.0f*(qx*qy + qw*qz);
        float R11 = 1.0f - 2.0f*(qx*qx + qz*qz);
        float R12 = 2.0f*(qy*qz - qw*qx);
        float R20 = 2.0f*(qx*qz - qw*qy);
        float R21 = 2.0f*(qy*qz + qw*qx);
        float R22 = 1.0f - 2.0f*(qx*qx + qy*qy);

        float s0 = scales[3*i], s1 = scales[3*i+1], s2 = scales[3*i+2];
        float M00 = R00*s0, M01 = R01*s1, M02 = R02*s2;
        float M10 = R10*s0, M11 = R11*s1, M12 = R12*s2;
        float M20 = R20*s0, M21 = R21*s1, M22 = R22*s2;

        float s00 = M00*M00 + M01*M01 + M02*M02;
        float s01 = M00*M10 + M01*M11 + M02*M12;
        float s02 = M00*M20 + M01*M21 + M02*M22;
        float s11 = M10*M10 + M11*M11 + M12*M12;
        float s12 = M10*M20 + M11*M21 + M12*M22;
        float s22 = M20*M20 + M21*M21 + M22*M22;

        float lim = 1.3f * tanfov;
        float invz = 1.0f / t2;
        float txc = fminf(fmaxf(t0*invz, -lim), lim) * t2;
        float tyc = fminf(fmaxf(t1*invz, -lim), lim) * t2;
        float J00 = fx*invz,  J02 = -fx*txc*invz*invz;
        float J11 = fy*invz,  J12 = -fy*tyc*invz*invz;

        float T00 = J00*V[0] + J02*V[8];
        float T01 = J00*V[1] + J02*V[9];
        float T02 = J00*V[2] + J02*V[10];
        float T10 = J11*V[4] + J12*V[8];
        float T11 = J11*V[5] + J12*V[9];
        float T12 = J11*V[6] + J12*V[10];

        float u0 = s00*T00 + s01*T01 + s02*T02;
        float u1 = s01*T00 + s11*T01 + s12*T02;
        float u2 = s02*T00 + s12*T01 + s22*T02;
        float cov00 = T00*u0 + T01*u1 + T02*u2;
        float cov01 = T10*u0 + T11*u1 + T12*u2;
        float v0 = s00*T10 + s01*T11 + s02*T12;
        float v1 = s01*T10 + s11*T11 + s12*T12;
        float v2 = s02*T10 + s12*T11 + s22*T12;
        float cov11 = T10*v0 + T11*v1 + T12*v2;

        float a = cov00 + 0.3f;
        float b = cov01;
        float c = cov11 + 0.3f;
        float det = a*c - b*b;
        bool valid = (depth > 0.2f) && (det > 0.0f);
        float det_s = valid ? det : 1.0f;
        float invdet = 1.0f / det_s;
        float ca = c * invdet;
        float cbn = -b * invdet;
        float cc = a * invdet;

        float mid = 0.5f * (a + c);
        float lam = mid + sqrtf(fmaxf(mid*mid - det, 0.1f));

        float op = ops[i];
        float cr  = fmaxf(SH_C0 * feats[3*i]   + 0.5f, 0.0f);
        float cg  = fmaxf(SH_C0 * feats[3*i+1] + 0.5f, 0.0f);
        float cbl = fmaxf(SH_C0 * feats[3*i+2] + 0.5f, 0.0f);

        if (lane == 0) {
            out_radii[i] = valid ? ceilf(3.0f * sqrtf(lam)) : 0.0f;
            g_SA[r]  = make_float4(px, py, -0.5f * ca, -cbn);
            g_SB[r]  = make_float4(-0.5f * cc, op, cr, cg);
            g_Scb[r] = cbl;
        }

        if (valid) {
            // contribution nonzero iff Q <= 2*tau, tau = ln(255*op)
            float tau = logf(255.0f * op) + 0.02f;
            float Qmax = 2.0f * tau + 0.1f;
            float dxm = sqrtf(fmaxf(2.0f * tau * a, 0.0f)) + 1.0f;
            float dym = sqrtf(fmaxf(2.0f * tau * c, 0.0f)) + 1.0f;
            int txl = max(0,       (int)floorf((px - dxm) * (1.0f / TW)));
            int txh = min(NTX - 1, (int)floorf((px + dxm) * (1.0f / TW)));
            int tyl = max(0,       (int)floorf((py - dym) * (1.0f / TH)));
            int tyh = min(NTY - 1, (int)floorf((py + dym) * (1.0f / TH)));

            if (txh >= txl && tyh >= tyl) {
                int bw = txh - txl + 1, bh = tyh - tyl + 1;
                int ntl = bw * bh;
                float rca = 1.0f / ca, rcc = 1.0f / cc;
                unsigned bit = 1u << (r & 31);
                int wofs = r >> 5;
                for (int k = lane; k < ntl; k += 32) {
                    int tx = txl + (k % bw);
                    int ty = tyl + (k / bw);
                    // d-range of tile pixels relative to the mean
                    float dxl = (float)(tx * TW) - px;
                    float dxh = (float)(tx * TW + TW - 1) - px;
                    float dyl = (float)(ty * TH) - py;
                    float dyh = (float)(ty * TH + TH - 1) - py;
                    // exact min of Q = ca*dx^2 + 2*cb*dx*dy + cc*dy^2 over box
                    float Qmin = 0.0f;
                    if (dxl > 0.0f || dxh < 0.0f || dyl > 0.0f || dyh < 0.0f) {
                        float q0, q1, q2, q3, dyb, dxb;
                        dyb = fminf(fmaxf(-cbn * dxl * rcc, dyl), dyh);
                        q0 = ca*dxl*dxl + 2.0f*cbn*dxl*dyb + cc*dyb*dyb;
                        dyb = fminf(fmaxf(-cbn * dxh * rcc, dyl), dyh);
                        q1 = ca*dxh*dxh + 2.0f*cbn*dxh*dyb + cc*dyb*dyb;
                        dxb = fminf(fmaxf(-cbn * dyl * rca, dxl), dxh);
                        q2 = ca*dxb*dxb + 2.0f*cbn*dxb*dyl + cc*dyl*dyl;
                        dxb = fminf(fmaxf(-cbn * dyh * rca, dxl), dxh);
                        q3 = ca*dxb*dxb + 2.0f*cbn*dxb*dyh + cc*dyh*dyh;
                        Qmin = fminf(fminf(q0, q1), fminf(q2, q3));
                    }
                    if (Qmin <= Qmax)
                        atomicOr(&g_mask[(ty * NTX + tx) * MWORDS + wofs], bit);
                }
            }
        }
    }
}

// ===========================================================================
// K2: render one 16x8 tile per block. 1024 threads = 8 list-segments x 128 px.
// Alpha blending composes associatively: (C,T)∘(C',T') = (C + T·C', T·T').
__global__ __launch_bounds__(RT)
void render_kernel(float* __restrict__ out)
{
    int tid  = threadIdx.x;
    int seg  = tid >> 7;          // 0..7
    int pix  = tid & 127;
    int tile = blockIdx.x;
    int x0 = (tile & (NTX - 1)) * TW;
    int y0 = (tile >> 3) * TH;
    float gx = (float)(x0 + (pix & 15));
    float gy = (float)(y0 + (pix >> 4));

    __shared__ unsigned smask[MWORDS];
    __shared__ int sofs[MWORDS + 1];
    __shared__ float4 lA[LISTCAP], lB[LISTCAP];
    __shared__ float  lCb[LISTCAP];
    __shared__ float  pC0[SEGS][128], pC1[SEGS][128], pC2[SEGS][128], pT[SEGS][128];
    __shared__ float  runT[128];

    if (tid < MWORDS) smask[tid] = g_mask[tile * MWORDS + tid];
    if (tid < 128) runT[tid] = 1.0f;
    __syncthreads();
    if (tid < MWORDS) g_mask[tile * MWORDS + tid] = 0u;   // replay-safe re-zero

    if (tid < 32) {
        int c0 = __popc(smask[tid]);
        int c1 = __popc(smask[tid + 32]);
        int s0 = c0, s1 = c1;
        #pragma unroll
        for (int d = 1; d < 32; d <<= 1) {
            int t0 = __shfl_up_sync(0xffffffffu, s0, d);
            int t1 = __shfl_up_sync(0xffffffffu, s1, d);
            if (tid >= d) { s0 += t0; s1 += t1; }
        }
        int tot0 = __shfl_sync(0xffffffffu, s0, 31);
        sofs[tid]      = s0 - c0;
        sofs[tid + 32] = tot0 + s1 - c1;
        if (tid == 31) sofs[64] = tot0 + s1;
    }
    __syncthreads();

    int total = sofs[MWORDS];
    const float ALPHA_MIN = 1.0f / 255.0f;

    float RC0 = 0.0f, RC1 = 0.0f, RC2 = 0.0f, RT_ = 1.0f;

    for (int base = 0; base < total; base += LISTCAP) {
        int idx = base + tid;
        if (idx < total) {
            int lo = 0, hi = MWORDS - 1;
            #pragma unroll
            for (int step = 0; step < 6; step++) {
                int mid = (lo + hi + 1) >> 1;
                if (sofs[mid] <= idx) lo = mid; else hi = mid - 1;
            }
            int w = lo;
            int k = idx - sofs[w];
            unsigned mm = smask[w];
            int pos = 0;
            int c;
            c = __popc(mm & 0xFFFFu); if (k >= c) { k -= c; mm >>= 16; pos += 16; }
            c = __popc(mm & 0xFFu);   if (k >= c) { k -= c; mm >>= 8;  pos += 8; }
            c = __popc(mm & 0xFu);    if (k >= c) { k -= c; mm >>= 4;  pos += 4; }
            c = __popc(mm & 0x3u);    if (k >= c) { k -= c; mm >>= 2;  pos += 2; }
            c = __popc(mm & 0x1u);    if (k >= c) {         pos += 1; }
            int j = w * 32 + pos;
            lA[tid]  = g_SA[j];
            lB[tid]  = g_SB[j];
            lCb[tid] = g_Scb[j];
        }
        __syncthreads();

        int cnt = min(LISTCAP, total - base);
        int q  = (cnt + SEGS - 1) / SEGS;
        int j0 = min(cnt, seg * q);
        int j1 = min(cnt, j0 + q);

        float c0 = 0.0f, c1 = 0.0f, c2 = 0.0f, t = 1.0f;
        if (runT[pix] > 1e-5f) {
            for (int j = j0; j < j1; j++) {
                float4 A = lA[j];
                float4 B = lB[j];
                float dx = gx - A.x, dy = gy - A.y;
                float power = fmaf(A.z * dx, dx, fmaf(B.x * dy, dy, A.w * dx * dy));
                if (power > 0.0f) continue;
                float alpha = fminf(0.99f, B.y * __expf(power));
                if (alpha < ALPHA_MIN) continue;
                float w = t * alpha;
                c0 = fmaf(w, B.z, c0);
                c1 = fmaf(w, B.w, c1);
                c2 = fmaf(w, lCb[j], c2);
                t *= (1.0f - alpha);
            }
        }
        pC0[seg][pix] = c0; pC1[seg][pix] = c1; pC2[seg][pix] = c2; pT[seg][pix] = t;
        __syncthreads();

        if (seg == 0) {
            #pragma unroll
            for (int s = 0; s < SEGS; s++) {
                RC0 = fmaf(RT_, pC0[s][pix], RC0);
                RC1 = fmaf(RT_, pC1[s][pix], RC1);
                RC2 = fmaf(RT_, pC2[s][pix], RC2);
                RT_ *= pT[s][pix];
            }
            runT[pix] = RT_;
        }
        int alive = __syncthreads_count((seg == 0) ? (RT_ > 1e-5f) : 0);
        if (alive == 0) break;
    }

    if (seg == 0) {
        int p = (y0 + (pix >> 4)) * IMG + x0 + (pix & 15);
        out[p]          = RC0 + RT_;
        out[NPIX + p]   = RC1 + RT_;
        out[2*NPIX + p] = RC2 + RT_;
    }
}

// ===========================================================================
extern "C" void kernel_launch(void* const* d_in, const int* in_sizes, int n_in,
                              void* d_out, int out_size)
{
    const float* means  = (const float*)d_in[0];
    const float* feats  = (const float*)d_in[2];
    const float* ops    = (const float*)d_in[3];
    const float* scales = (const float*)d_in[4];
    const float* rots   = (const float*)d_in[5];
    const float* V      = (const float*)d_in[6];
    const float* PM     = (const float*)d_in[7];

    float* out = (float*)d_out;

    prep_kernel<<<128, 256>>>(means, feats, ops, scales, rots, V, PM, out);
    render_kernel<<<NTILES, RT>>>(out);
}